// round 4
// baseline (speedup 1.0000x reference)
#include <cuda_runtime.h>
#include <math.h>

// ---------------------------------------------------------------------------
// CharRNN: x=emb[ids]; xin = x@W_in^T + bias;  W_eff = W_h - W_h^T - diff*I
// 1024x: h = h + dt*(h@W_eff^T + xin[s]);  out = softmax((h@fc_w^T + fc_b)/T)
// R3: R1 numerics were correct (median 49.9ms) but 2053 graph nodes left a
// 4MB driver upload buffer live after teardown -> rule violation. This round
// collapses the 1024-step loop into ONE persistent kernel (128 CTAs, software
// grid barrier), shrinking the graph to 6 nodes.
// ---------------------------------------------------------------------------

#define SEQ    1024
#define BATCH  128
#define HID    2048
#define EMB    512
#define VOCAB  50257
#define LDL    50260          // padded logits row stride (multiple of 4)
#define DT     0.01f
#define DIFF   0.001f
#define KSPLIT 4
#define NCTA   128            // persistent grid size (<= 148 SMs, co-resident)

#define BM 128
#define BN 64
#define BK 16

// scratch (static device globals; allocation APIs are forbidden)
__device__ float g_xin[(size_t)SEQ * BATCH * HID];   // 1.07 GB
__device__ float g_weff[(size_t)HID * HID];          // dt*(Wh - Wh^T - diff*I)
__device__ float g_h[2][BATCH * HID];                // ping-pong
__device__ float g_acc[KSPLIT][BATCH * HID];         // split-K partials
__device__ float g_logits[(size_t)BATCH * LDL];      // padded rows, 16B-aligned
__device__ unsigned g_bar_gen;                       // grid barrier generation
__device__ unsigned g_bar_cnt;                       // grid barrier counter

// ---------------------------------------------------------------------------
__global__ void build_weff_kernel(const float* __restrict__ Wh) {
    int idx = blockIdx.x * blockDim.x + threadIdx.x;
    if (idx < HID * HID) {
        int i = idx / HID, j = idx % HID;
        float v = Wh[idx] - Wh[j * HID + i];
        if (i == j) v -= DIFF;
        g_weff[idx] = DT * v;           // fold Euler dt into the matrix
    }
}

__global__ void init_h_kernel(const float* __restrict__ h0) {
    int i = blockIdx.x * blockDim.x + threadIdx.x;
    if (i < BATCH * HID) g_h[0][i] = h0[i];
}

// ---------------------------------------------------------------------------
// Generic NT GEMM: C[m,n] = sum_k A[m,k]*B[n,k] (+ bias[n]).
// A rows optionally gathered through gidx (embedding lookup fusion).
// M multiple of BM, K multiple of BK, N bounds-checked, ldc % 4 == 0.
// grid = (ceil(N/BN), M/BM), block = 256.
// ---------------------------------------------------------------------------
template <bool GATHER, bool HAS_BIAS>
__global__ __launch_bounds__(256) void gemm_nt_kernel(
    const float* __restrict__ A, const int* __restrict__ gidx,
    const float* __restrict__ B, const float* __restrict__ bias,
    float* __restrict__ C, int N, int K, int ldc)
{
    __shared__ float As[BK][BM];
    __shared__ float Bs[BK][BN];

    const int tid = threadIdx.x;
    const int m0 = blockIdx.y * BM;
    const int n0 = blockIdx.x * BN;
    const int tr = tid >> 4;        // 0..15
    const int tc = tid & 15;        // 0..15

    const int ar0 = tid >> 2;       // 0..63
    const int ar1 = ar0 + 64;
    const int ac4 = tid & 3;        // float4 column within BK

    const float* arow0;
    const float* arow1;
    if (GATHER) {
        arow0 = A + (size_t)gidx[m0 + ar0] * K;
        arow1 = A + (size_t)gidx[m0 + ar1] * K;
    } else {
        arow0 = A + (size_t)(m0 + ar0) * K;
        arow1 = A + (size_t)(m0 + ar1) * K;
    }

    const int   br     = tid >> 2;  // 0..63
    const bool  bvalid = (n0 + br) < N;
    const float* brow  = B + (size_t)(bvalid ? (n0 + br) : 0) * K;

    float acc[8][4];
    #pragma unroll
    for (int i = 0; i < 8; i++)
        #pragma unroll
        for (int j = 0; j < 4; j++) acc[i][j] = 0.f;

    for (int kt = 0; kt < K; kt += BK) {
        float4 va0 = *(const float4*)(arow0 + kt + ac4 * 4);
        float4 va1 = *(const float4*)(arow1 + kt + ac4 * 4);
        float4 vb  = bvalid ? *(const float4*)(brow + kt + ac4 * 4)
                            : make_float4(0.f, 0.f, 0.f, 0.f);
        __syncthreads();
        As[ac4 * 4 + 0][ar0] = va0.x;
        As[ac4 * 4 + 1][ar0] = va0.y;
        As[ac4 * 4 + 2][ar0] = va0.z;
        As[ac4 * 4 + 3][ar0] = va0.w;
        As[ac4 * 4 + 0][ar1] = va1.x;
        As[ac4 * 4 + 1][ar1] = va1.y;
        As[ac4 * 4 + 2][ar1] = va1.z;
        As[ac4 * 4 + 3][ar1] = va1.w;
        Bs[ac4 * 4 + 0][br] = vb.x;
        Bs[ac4 * 4 + 1][br] = vb.y;
        Bs[ac4 * 4 + 2][br] = vb.z;
        Bs[ac4 * 4 + 3][br] = vb.w;
        __syncthreads();

        #pragma unroll
        for (int k = 0; k < BK; k++) {
            float4 a0 = *(const float4*)&As[k][tr * 8];
            float4 a1 = *(const float4*)&As[k][tr * 8 + 4];
            float4 b4 = *(const float4*)&Bs[k][tc * 4];
            float av[8] = {a0.x, a0.y, a0.z, a0.w, a1.x, a1.y, a1.z, a1.w};
            float bv[4] = {b4.x, b4.y, b4.z, b4.w};
            #pragma unroll
            for (int i = 0; i < 8; i++)
                #pragma unroll
                for (int j = 0; j < 4; j++)
                    acc[i][j] = fmaf(av[i], bv[j], acc[i][j]);
        }
    }

    if (n0 + BN <= N) {
        #pragma unroll
        for (int i = 0; i < 8; i++) {
            int r = m0 + tr * 8 + i;
            int n = n0 + tc * 4;
            float4 st;
            if (HAS_BIAS) {
                st = make_float4(acc[i][0] + bias[n + 0], acc[i][1] + bias[n + 1],
                                 acc[i][2] + bias[n + 2], acc[i][3] + bias[n + 3]);
            } else {
                st = make_float4(acc[i][0], acc[i][1], acc[i][2], acc[i][3]);
            }
            *(float4*)(C + (size_t)r * ldc + n) = st;
        }
    } else {
        #pragma unroll
        for (int i = 0; i < 8; i++) {
            int r = m0 + tr * 8 + i;
            #pragma unroll
            for (int j = 0; j < 4; j++) {
                int n = n0 + tc * 4 + j;
                if (n < N)
                    C[(size_t)r * ldc + n] = acc[i][j] + (HAS_BIAS ? bias[n] : 0.f);
            }
        }
    }
}

// ---------------------------------------------------------------------------
// Software grid barrier for the persistent kernel (all NCTA CTAs co-resident).
// Release: __threadfence before arrive. Acquire: fence after generation flip.
// ---------------------------------------------------------------------------
__device__ __forceinline__ void grid_barrier()
{
    __syncthreads();
    if (threadIdx.x == 0) {
        __threadfence();
        unsigned gen = *(volatile unsigned*)&g_bar_gen;
        unsigned arrived = atomicAdd(&g_bar_cnt, 1u);
        if (arrived == NCTA - 1) {
            g_bar_cnt = 0;
            __threadfence();
            *(volatile unsigned*)&g_bar_gen = gen + 1;
        } else {
            while (*(volatile unsigned*)&g_bar_gen == gen) { }
        }
        __threadfence();
    }
    __syncthreads();
}

// ---------------------------------------------------------------------------
// Persistent recurrence: 1024 x { split-K step GEMM -> barrier -> epilogue ->
// barrier }. CTA (jt = bid>>2, ks = bid&3): partial over K slice ks for
// column tile jt. Cross-CTA data read via __ldcg (L2; L1 is not coherent).
// After the loop, final h is in g_h[0] (SEQ even).
// ---------------------------------------------------------------------------
__global__ __launch_bounds__(256) void rnn_persistent_kernel()
{
    __shared__ float As[BK][BM];
    __shared__ float Bs[BK][BN];

    const int tid = threadIdx.x;
    const int bid = blockIdx.x;
    const int jt  = bid >> 2;            // 0..31 column tile
    const int ks  = bid & 3;             // 0..3  K slice
    const int n0  = jt * BN;
    const int kb  = ks * (HID / KSPLIT);

    const int tr = tid >> 4;             // 0..15
    const int tc = tid & 15;             // 0..15
    const int ar0 = tid >> 2;            // 0..63
    const int ar1 = ar0 + 64;
    const int ac4 = tid & 3;

    const float* brow = g_weff + (size_t)(n0 + ar0) * HID;   // B row per thread
    float* __restrict__ dst = g_acc[ks];

    // epilogue mapping: each CTA owns one batch row (2048 elems), 8 per thread
    const int erow  = bid;               // batch index
    const int ebase = erow * HID + tid * 8;

    for (int t = 0; t < SEQ; t++) {
        const int p = t & 1;
        const float* __restrict__ A = g_h[p];
        const float* arow0 = A + (size_t)ar0 * HID;
        const float* arow1 = A + (size_t)ar1 * HID;

        float acc[8][4];
        #pragma unroll
        for (int i = 0; i < 8; i++)
            #pragma unroll
            for (int j = 0; j < 4; j++) acc[i][j] = 0.f;

        for (int kt = kb; kt < kb + HID / KSPLIT; kt += BK) {
            float4 va0 = __ldcg((const float4*)(arow0 + kt + ac4 * 4));
            float4 va1 = __ldcg((const float4*)(arow1 + kt + ac4 * 4));
            float4 vb  = *(const float4*)(brow + kt + ac4 * 4);
            __syncthreads();
            As[ac4 * 4 + 0][ar0] = va0.x;
            As[ac4 * 4 + 1][ar0] = va0.y;
            As[ac4 * 4 + 2][ar0] = va0.z;
            As[ac4 * 4 + 3][ar0] = va0.w;
            As[ac4 * 4 + 0][ar1] = va1.x;
            As[ac4 * 4 + 1][ar1] = va1.y;
            As[ac4 * 4 + 2][ar1] = va1.z;
            As[ac4 * 4 + 3][ar1] = va1.w;
            Bs[ac4 * 4 + 0][ar0] = vb.x;
            Bs[ac4 * 4 + 1][ar0] = vb.y;
            Bs[ac4 * 4 + 2][ar0] = vb.z;
            Bs[ac4 * 4 + 3][ar0] = vb.w;
            __syncthreads();

            #pragma unroll
            for (int k = 0; k < BK; k++) {
                float4 a0 = *(const float4*)&As[k][tr * 8];
                float4 a1 = *(const float4*)&As[k][tr * 8 + 4];
                float4 b4 = *(const float4*)&Bs[k][tc * 4];
                float av[8] = {a0.x, a0.y, a0.z, a0.w, a1.x, a1.y, a1.z, a1.w};
                float bv[4] = {b4.x, b4.y, b4.z, b4.w};
                #pragma unroll
                for (int i = 0; i < 8; i++)
                    #pragma unroll
                    for (int j = 0; j < 4; j++)
                        acc[i][j] = fmaf(av[i], bv[j], acc[i][j]);
            }
        }

        #pragma unroll
        for (int i = 0; i < 8; i++) {
            int r = tr * 8 + i;
            *(float4*)(dst + (size_t)r * HID + n0 + tc * 4) =
                make_float4(acc[i][0], acc[i][1], acc[i][2], acc[i][3]);
        }

        grid_barrier();   // all partials visible

        // h_new[i] = h[i] + sum_ks acc[ks][i] + dt * xin[t][i]
        {
            const float* __restrict__ xrow = g_xin + (size_t)t * BATCH * HID;
            float* __restrict__ hout = g_h[p ^ 1];
            #pragma unroll
            for (int q = 0; q < 2; q++) {
                int i = ebase + q * 4;
                float4 s0 = __ldcg((const float4*)(g_acc[0] + i));
                float4 s1 = __ldcg((const float4*)(g_acc[1] + i));
                float4 s2 = __ldcg((const float4*)(g_acc[2] + i));
                float4 s3 = __ldcg((const float4*)(g_acc[3] + i));
                float4 hv = __ldcg((const float4*)(g_h[p] + i));
                float4 xv = *(const float4*)(xrow + i);
                float4 o;
                o.x = hv.x + (s0.x + s1.x + s2.x + s3.x) + DT * xv.x;
                o.y = hv.y + (s0.y + s1.y + s2.y + s3.y) + DT * xv.y;
                o.z = hv.z + (s0.z + s1.z + s2.z + s3.z) + DT * xv.z;
                o.w = hv.w + (s0.w + s1.w + s2.w + s3.w) + DT * xv.w;
                *(float4*)(hout + i) = o;
            }
        }

        grid_barrier();   // h_new visible before next step reads it
    }
}

// ---------------------------------------------------------------------------
__global__ __launch_bounds__(256) void softmax_kernel(const void* __restrict__ temp_raw,
                                                      float* __restrict__ out)
{
    __shared__ float red[256];
    const int b = blockIdx.x;
    const int tid = threadIdx.x;
    const float* __restrict__ row = g_logits + (size_t)b * LDL;
    float* __restrict__ orow = out + (size_t)b * VOCAB;

    // temperature may arrive as int32 or float32 scalar; decode defensively
    float T = 1.0f;
    if (temp_raw) {
        int iv = *(const int*)temp_raw;
        float fv = __int_as_float(iv);
        if (iv >= 1 && iv <= 1000000) T = (float)iv;
        else if (fv > 1e-8f && fv < 1e8f) T = fv;
    }
    const float invT = 1.0f / T;

    float m = -3.4e38f;
    for (int v = tid; v < VOCAB; v += 256) m = fmaxf(m, row[v]);
    red[tid] = m; __syncthreads();
    for (int s = 128; s > 0; s >>= 1) {
        if (tid < s) red[tid] = fmaxf(red[tid], red[tid + s]);
        __syncthreads();
    }
    const float mx = red[0];
    __syncthreads();

    float sum = 0.f;
    for (int v = tid; v < VOCAB; v += 256) {
        float e = expf((row[v] - mx) * invT);
        orow[v] = e;
        sum += e;
    }
    red[tid] = sum; __syncthreads();
    for (int s = 128; s > 0; s >>= 1) {
        if (tid < s) red[tid] += red[tid + s];
        __syncthreads();
    }
    const float inv = 1.0f / red[0];
    for (int v = tid; v < VOCAB; v += 256) orow[v] *= inv;
}

// ---------------------------------------------------------------------------
extern "C" void kernel_launch(void* const* d_in, const int* in_sizes, int n_in,
                              void* d_out, int out_size)
{
    const int*   ids    = (const int*)d_in[0];    // [1024,128]
    const float* h_init = (const float*)d_in[1];  // [128,2048]
    const float* emb    = (const float*)d_in[2];  // [50257,512]
    const float* W_in   = (const float*)d_in[3];  // [2048,512]
    const float* W_h    = (const float*)d_in[4];  // [2048,2048]
    const float* bias   = (const float*)d_in[5];  // [2048]
    const float* fc_w   = (const float*)d_in[6];  // [50257,2048]
    const float* fc_b   = (const float*)d_in[7];  // [50257]
    const void*  temp   = (n_in > 8) ? d_in[8] : nullptr;
    float*       out    = (float*)d_out;

    void *xin_ptr, *h_ptr, *logits_ptr;
    cudaGetSymbolAddress(&xin_ptr, g_xin);
    cudaGetSymbolAddress(&h_ptr, g_h);
    cudaGetSymbolAddress(&logits_ptr, g_logits);

    build_weff_kernel<<<(HID * HID + 255) / 256, 256>>>(W_h);
    init_h_kernel<<<(BATCH * HID + 255) / 256, 256>>>(h_init);

    // xin = gather(emb, ids) @ W_in^T + bias : M=131072, N=2048, K=512
    {
        dim3 grid(HID / BN, (SEQ * BATCH) / BM);
        gemm_nt_kernel<true, true><<<grid, 256>>>(
            emb, ids, W_in, bias, (float*)xin_ptr, HID, EMB, HID);
    }

    // 1024 sequential Euler steps in ONE persistent kernel (6-node graph)
    rnn_persistent_kernel<<<NCTA, 256>>>();

    // logits = h @ fc_w^T + fc_b : M=128, N=50257, K=2048 (ldc padded)
    {
        dim3 grid((VOCAB + BN - 1) / BN, BATCH / BM);
        gemm_nt_kernel<false, true><<<grid, 256>>>(
            (const float*)h_ptr, nullptr, fc_w, fc_b, (float*)logits_ptr,
            VOCAB, HID, LDL);
    }

    softmax_kernel<<<BATCH, 256>>>(temp, out);
}

// round 10
// speedup vs baseline: 1.8301x; 1.8301x over previous
#include <cuda_runtime.h>
#include <cuda_bf16.h>
#include <stdint.h>
#include <math.h>

// ---------------------------------------------------------------------------
// CharRNN on GB300 (sm_103). R7: tcgen05 is NOT available (harness PTX target
// is sm_103 without the 'a' suffix), so the recurrence uses warp-level
// mma.sync.m16n8k16 bf16 (HMMA) + ldmatrix instead.
// h_{t+1} = h_t + (h_t @ G^T) + dt*xin[t],  G = dt*(Wh - Wh^T - diff*I)
// Persistent kernel, 128 CTAs (jt 0..31 x ks 0..3): tile M=128 x N=64 x K=512.
// bf16x3 hi/lo split: D += Ahi*Bhi + Ahi*Blo + Alo*Bhi (fp32 reg accum).
// B (bf16 hi+lo) resident in SMEM for all steps; A staged per step in 4
// chunks of K=128. Split-K partials via gmem + software grid barrier.
// ---------------------------------------------------------------------------

#define SEQ    1024
#define BATCH  128
#define HID    2048
#define EMB    512
#define VOCAB  50257
#define LDL    50260
#define DT     0.01f
#define DIFF   0.001f
#define KSPLIT 4
#define NCTA   128

#define BM 128
#define BN 64
#define BK 16

// SMEM layout (bytes). Padded rows for conflict-free ldmatrix:
// B: 64 rows x 520 bf16 (stride 1040B = 65x16B, mod8=1)
// A: 128 rows x 136 bf16 (stride 272B = 17x16B, mod8=1)
#define SM_B_HI  0
#define SM_B_LO  66560
#define SM_A_HI  133120
#define SM_A_LO  167936
#define SM_TOTAL 202752

// scratch
__device__ float g_xin[(size_t)SEQ * BATCH * HID];
__device__ float g_weff[(size_t)HID * HID];          // G = dt*(Wh-Wh^T-diff I)
__device__ float g_h[2][BATCH * HID];
__device__ float g_acc[KSPLIT][BATCH * HID];
__device__ float g_logits[(size_t)BATCH * LDL];
__device__ unsigned g_bar_gen;
__device__ unsigned g_bar_cnt;

// ---------------------------------------------------------------------------
__device__ __forceinline__ uint32_t smem_u32(const void* p) {
    uint32_t a;
    asm("{ .reg .u64 t; cvta.to.shared.u64 t, %1; cvt.u32.u64 %0, t; }"
        : "=r"(a) : "l"(p));
    return a;
}

#define LDSM_X4(r, addr) \
    asm volatile("ldmatrix.sync.aligned.m8n8.x4.shared.b16 {%0,%1,%2,%3}, [%4];" \
        : "=r"((r)[0]), "=r"((r)[1]), "=r"((r)[2]), "=r"((r)[3]) \
        : "r"(addr))

#define MMA16816(c, a, b) \
    asm volatile("mma.sync.aligned.m16n8k16.row.col.f32.bf16.bf16.f32 " \
        "{%0,%1,%2,%3}, {%4,%5,%6,%7}, {%8,%9}, {%0,%1,%2,%3};" \
        : "+f"((c)[0]), "+f"((c)[1]), "+f"((c)[2]), "+f"((c)[3]) \
        : "r"((a)[0]), "r"((a)[1]), "r"((a)[2]), "r"((a)[3]), \
          "r"((b)[0]), "r"((b)[1]))

// ---------------------------------------------------------------------------
__global__ void build_weff_kernel(const float* __restrict__ Wh) {
    int idx = blockIdx.x * blockDim.x + threadIdx.x;
    if (idx < HID * HID) {
        int i = idx / HID, j = idx % HID;
        float v = Wh[idx] - Wh[j * HID + i];
        if (i == j) v -= DIFF;
        g_weff[idx] = DT * v;
    }
}

__global__ void init_h_kernel(const float* __restrict__ h0) {
    int i = blockIdx.x * blockDim.x + threadIdx.x;
    if (i < BATCH * HID) g_h[0][i] = h0[i];
}

// ---------------------------------------------------------------------------
// fp32 NT GEMM (xin + logits), proven in R3
// ---------------------------------------------------------------------------
template <bool GATHER, bool HAS_BIAS>
__global__ __launch_bounds__(256) void gemm_nt_kernel(
    const float* __restrict__ A, const int* __restrict__ gidx,
    const float* __restrict__ B, const float* __restrict__ bias,
    float* __restrict__ C, int N, int K, int ldc)
{
    __shared__ float As[BK][BM];
    __shared__ float Bs[BK][BN];

    const int tid = threadIdx.x;
    const int m0 = blockIdx.y * BM;
    const int n0 = blockIdx.x * BN;
    const int tr = tid >> 4;
    const int tc = tid & 15;
    const int ar0 = tid >> 2;
    const int ar1 = ar0 + 64;
    const int ac4 = tid & 3;

    const float* arow0;
    const float* arow1;
    if (GATHER) {
        arow0 = A + (size_t)gidx[m0 + ar0] * K;
        arow1 = A + (size_t)gidx[m0 + ar1] * K;
    } else {
        arow0 = A + (size_t)(m0 + ar0) * K;
        arow1 = A + (size_t)(m0 + ar1) * K;
    }
    const int   br     = tid >> 2;
    const bool  bvalid = (n0 + br) < N;
    const float* brow  = B + (size_t)(bvalid ? (n0 + br) : 0) * K;

    float acc[8][4];
    #pragma unroll
    for (int i = 0; i < 8; i++)
        #pragma unroll
        for (int j = 0; j < 4; j++) acc[i][j] = 0.f;

    for (int kt = 0; kt < K; kt += BK) {
        float4 va0 = *(const float4*)(arow0 + kt + ac4 * 4);
        float4 va1 = *(const float4*)(arow1 + kt + ac4 * 4);
        float4 vb  = bvalid ? *(const float4*)(brow + kt + ac4 * 4)
                            : make_float4(0.f, 0.f, 0.f, 0.f);
        __syncthreads();
        As[ac4 * 4 + 0][ar0] = va0.x; As[ac4 * 4 + 1][ar0] = va0.y;
        As[ac4 * 4 + 2][ar0] = va0.z; As[ac4 * 4 + 3][ar0] = va0.w;
        As[ac4 * 4 + 0][ar1] = va1.x; As[ac4 * 4 + 1][ar1] = va1.y;
        As[ac4 * 4 + 2][ar1] = va1.z; As[ac4 * 4 + 3][ar1] = va1.w;
        Bs[ac4 * 4 + 0][br] = vb.x;  Bs[ac4 * 4 + 1][br] = vb.y;
        Bs[ac4 * 4 + 2][br] = vb.z;  Bs[ac4 * 4 + 3][br] = vb.w;
        __syncthreads();

        #pragma unroll
        for (int k = 0; k < BK; k++) {
            float4 a0 = *(const float4*)&As[k][tr * 8];
            float4 a1 = *(const float4*)&As[k][tr * 8 + 4];
            float4 b4 = *(const float4*)&Bs[k][tc * 4];
            float av[8] = {a0.x, a0.y, a0.z, a0.w, a1.x, a1.y, a1.z, a1.w};
            float bv[4] = {b4.x, b4.y, b4.z, b4.w};
            #pragma unroll
            for (int i = 0; i < 8; i++)
                #pragma unroll
                for (int j = 0; j < 4; j++)
                    acc[i][j] = fmaf(av[i], bv[j], acc[i][j]);
        }
    }

    if (n0 + BN <= N) {
        #pragma unroll
        for (int i = 0; i < 8; i++) {
            int r = m0 + tr * 8 + i;
            int n = n0 + tc * 4;
            float4 st;
            if (HAS_BIAS) {
                st = make_float4(acc[i][0] + bias[n + 0], acc[i][1] + bias[n + 1],
                                 acc[i][2] + bias[n + 2], acc[i][3] + bias[n + 3]);
            } else {
                st = make_float4(acc[i][0], acc[i][1], acc[i][2], acc[i][3]);
            }
            *(float4*)(C + (size_t)r * ldc + n) = st;
        }
    } else {
        #pragma unroll
        for (int i = 0; i < 8; i++) {
            int r = m0 + tr * 8 + i;
            #pragma unroll
            for (int j = 0; j < 4; j++) {
                int n = n0 + tc * 4 + j;
                if (n < N)
                    C[(size_t)r * ldc + n] = acc[i][j] + (HAS_BIAS ? bias[n] : 0.f);
            }
        }
    }
}

// ---------------------------------------------------------------------------
__device__ __forceinline__ void grid_barrier()
{
    __syncthreads();
    if (threadIdx.x == 0) {
        __threadfence();
        unsigned gen = *(volatile unsigned*)&g_bar_gen;
        unsigned arrived = atomicAdd(&g_bar_cnt, 1u);
        if (arrived == NCTA - 1) {
            g_bar_cnt = 0;
            __threadfence();
            *(volatile unsigned*)&g_bar_gen = gen + 1;
        } else {
            while (*(volatile unsigned*)&g_bar_gen == gen) { }
        }
        __threadfence();
    }
    __syncthreads();
}

// ---------------------------------------------------------------------------
// Persistent HMMA recurrence.
// Warp layout: wid>>1 -> m-group (32 rows), wid&1 -> n-group (32 cols).
// Per k16: 8 ldmatrix.x4 (A hi/lo x2 m16-tiles, B hi/lo x2 n8-pairs), 24 MMAs.
// ---------------------------------------------------------------------------
__global__ __launch_bounds__(256) void rnn_persistent_kernel()
{
    extern __shared__ char smem[];
    const uint32_t smem_base = smem_u32(smem);
    const int tid  = threadIdx.x;
    const int wid  = tid >> 5;
    const int lane = tid & 31;
    const int bid  = blockIdx.x;
    const int jt   = bid >> 2;
    const int ks   = bid & 3;
    const int n0   = jt * BN;
    const int kb   = ks * (HID / KSPLIT);   // 512-wide K slice

    // --- stage B = G[n0:n0+64, kb:kb+512] bf16 hi+lo (once) ---
    for (int i = tid; i < BN * 512; i += 256) {
        int n = i >> 9, k = i & 511;
        float w = g_weff[(size_t)(n0 + n) * HID + kb + k];
        __nv_bfloat16 hi = __float2bfloat16_rn(w);
        __nv_bfloat16 lo = __float2bfloat16_rn(w - __bfloat162float(hi));
        *(__nv_bfloat16*)(smem + SM_B_HI + n * 1040 + k * 2) = hi;
        *(__nv_bfloat16*)(smem + SM_B_LO + n * 1040 + k * 2) = lo;
    }
    __syncthreads();

    // ldmatrix lane offsets (bytes within A/B buffers)
    const int mw = (wid >> 1) * 32;          // warp m base (rows)
    const int nw = (wid & 1) * 32;           // warp n base (cols within BN)
    const uint32_t a_row  = (uint32_t)(mw + (lane & 15));
    const uint32_t a_koff = (lane & 16) ? 16u : 0u;
    const uint32_t a_off0 = a_row * 272 + a_koff;
    const uint32_t a_off1 = (a_row + 16) * 272 + a_koff;
    const uint32_t b_row  = (uint32_t)((lane & 7) + ((lane & 16) ? 8 : 0));
    const uint32_t b_koff = (lane & 8) ? 16u : 0u;
    const uint32_t b_off0 = (uint32_t)(nw + 0  + b_row) * 1040 + b_koff;
    const uint32_t b_off1 = (uint32_t)(nw + 16 + b_row) * 1040 + b_koff;

    const uint32_t ahi_b = smem_base + SM_A_HI;
    const uint32_t alo_b = smem_base + SM_A_LO;
    const uint32_t bhi_b = smem_base + SM_B_HI;
    const uint32_t blo_b = smem_base + SM_B_LO;

    const int ebase = bid * HID + tid * 8;   // epilogue: CTA owns batch row bid

    for (int t = 0; t < SEQ; t++) {
        const int p = t & 1;
        const float* __restrict__ hsrc = g_h[p];

        float c[2][4][4];
        #pragma unroll
        for (int i = 0; i < 2; i++)
            #pragma unroll
            for (int j = 0; j < 4; j++)
                #pragma unroll
                for (int q = 0; q < 4; q++) c[i][j][q] = 0.f;

        // 4 chunks of K=128
        for (int ch = 0; ch < 4; ch++) {
            __syncthreads();   // prior chunk's ldmatrix done before overwrite
            // stage A chunk: h[0:128, kb+ch*128 .. +127] -> bf16 hi/lo
            for (int i = tid; i < 4096; i += 256) {
                int m = i >> 5;
                int kk4 = (i & 31) * 4;
                float4 v = __ldcg((const float4*)(hsrc + (size_t)m * HID
                                                  + kb + ch * 128 + kk4));
                __nv_bfloat162 h01 = __float22bfloat162_rn(make_float2(v.x, v.y));
                __nv_bfloat162 h23 = __float22bfloat162_rn(make_float2(v.z, v.w));
                float2 f01 = __bfloat1622float2(h01);
                float2 f23 = __bfloat1622float2(h23);
                __nv_bfloat162 l01 = __float22bfloat162_rn(
                    make_float2(v.x - f01.x, v.y - f01.y));
                __nv_bfloat162 l23 = __float22bfloat162_rn(
                    make_float2(v.z - f23.x, v.w - f23.y));
                uint32_t off = (uint32_t)(m * 272 + kk4 * 2);
                *(uint2*)(smem + SM_A_HI + off) = make_uint2(
                    *(uint32_t*)&h01, *(uint32_t*)&h23);
                *(uint2*)(smem + SM_A_LO + off) = make_uint2(
                    *(uint32_t*)&l01, *(uint32_t*)&l23);
            }
            __syncthreads();

            const uint32_t bko = (uint32_t)(ch * 256);  // 128 bf16 = 256 bytes
            #pragma unroll
            for (int k16 = 0; k16 < 8; k16++) {
                const uint32_t ak = (uint32_t)(k16 * 32);
                const uint32_t bk = bko + (uint32_t)(k16 * 32);
                uint32_t ah0[4], ah1[4], al0[4], al1[4];
                uint32_t bh[8], bl[8];
                LDSM_X4(ah0, ahi_b + a_off0 + ak);
                LDSM_X4(ah1, ahi_b + a_off1 + ak);
                LDSM_X4(al0, alo_b + a_off0 + ak);
                LDSM_X4(al1, alo_b + a_off1 + ak);
                LDSM_X4(bh + 0, bhi_b + b_off0 + bk);   // n8 tiles 0,1
                LDSM_X4(bh + 4, bhi_b + b_off1 + bk);   // n8 tiles 2,3
                LDSM_X4(bl + 0, blo_b + b_off0 + bk);
                LDSM_X4(bl + 4, blo_b + b_off1 + bk);

                #pragma unroll
                for (int j = 0; j < 4; j++) {
                    MMA16816(c[0][j], ah0, bh + j * 2);
                    MMA16816(c[1][j], ah1, bh + j * 2);
                    MMA16816(c[0][j], ah0, bl + j * 2);
                    MMA16816(c[1][j], ah1, bl + j * 2);
                    MMA16816(c[0][j], al0, bh + j * 2);
                    MMA16816(c[1][j], al1, bh + j * 2);
                }
            }
        }

        // write partials: warp tile 32x32 at (mw, n0+nw)
        {
            float* __restrict__ dst = g_acc[ks];
            #pragma unroll
            for (int i = 0; i < 2; i++) {
                int row = mw + i * 16 + (lane >> 2);
                #pragma unroll
                for (int j = 0; j < 4; j++) {
                    int col = n0 + nw + j * 8 + (lane & 3) * 2;
                    *(float2*)(dst + (size_t)row * HID + col) =
                        make_float2(c[i][j][0], c[i][j][1]);
                    *(float2*)(dst + (size_t)(row + 8) * HID + col) =
                        make_float2(c[i][j][2], c[i][j][3]);
                }
            }
        }

        grid_barrier();   // partials visible chip-wide

        // h_new[i] = h[i] + sum_ks acc[ks][i] + dt * xin[t][i]
        {
            const float* __restrict__ xrow = g_xin + (size_t)t * BATCH * HID;
            float* __restrict__ hout = g_h[p ^ 1];
            #pragma unroll
            for (int q = 0; q < 2; q++) {
                int i = ebase + q * 4;
                float4 s0 = __ldcg((const float4*)(g_acc[0] + i));
                float4 s1 = __ldcg((const float4*)(g_acc[1] + i));
                float4 s2 = __ldcg((const float4*)(g_acc[2] + i));
                float4 s3 = __ldcg((const float4*)(g_acc[3] + i));
                float4 hv = __ldcg((const float4*)(g_h[p] + i));
                float4 xv = *(const float4*)(xrow + i);
                float4 o;
                o.x = hv.x + (s0.x + s1.x + s2.x + s3.x) + DT * xv.x;
                o.y = hv.y + (s0.y + s1.y + s2.y + s3.y) + DT * xv.y;
                o.z = hv.z + (s0.z + s1.z + s2.z + s3.z) + DT * xv.z;
                o.w = hv.w + (s0.w + s1.w + s2.w + s3.w) + DT * xv.w;
                *(float4*)(hout + i) = o;
            }
        }

        grid_barrier();   // h_new visible before next step's staging
    }
}

// ---------------------------------------------------------------------------
__global__ __launch_bounds__(256) void softmax_kernel(const void* __restrict__ temp_raw,
                                                      float* __restrict__ out)
{
    __shared__ float red[256];
    const int b = blockIdx.x;
    const int tid = threadIdx.x;
    const float* __restrict__ row = g_logits + (size_t)b * LDL;
    float* __restrict__ orow = out + (size_t)b * VOCAB;

    float T = 1.0f;
    if (temp_raw) {
        int iv = *(const int*)temp_raw;
        float fv = __int_as_float(iv);
        if (iv >= 1 && iv <= 1000000) T = (float)iv;
        else if (fv > 1e-8f && fv < 1e8f) T = fv;
    }
    const float invT = 1.0f / T;

    float m = -3.4e38f;
    for (int v = tid; v < VOCAB; v += 256) m = fmaxf(m, row[v]);
    red[tid] = m; __syncthreads();
    for (int s = 128; s > 0; s >>= 1) {
        if (tid < s) red[tid] = fmaxf(red[tid], red[tid + s]);
        __syncthreads();
    }
    const float mx = red[0];
    __syncthreads();

    float sum = 0.f;
    for (int v = tid; v < VOCAB; v += 256) {
        float e = expf((row[v] - mx) * invT);
        orow[v] = e;
        sum += e;
    }
    red[tid] = sum; __syncthreads();
    for (int s = 128; s > 0; s >>= 1) {
        if (tid < s) red[tid] += red[tid + s];
        __syncthreads();
    }
    const float inv = 1.0f / red[0];
    for (int v = tid; v < VOCAB; v += 256) orow[v] *= inv;
}

// ---------------------------------------------------------------------------
extern "C" void kernel_launch(void* const* d_in, const int* in_sizes, int n_in,
                              void* d_out, int out_size)
{
    const int*   ids    = (const int*)d_in[0];
    const float* h_init = (const float*)d_in[1];
    const float* emb    = (const float*)d_in[2];
    const float* W_in   = (const float*)d_in[3];
    const float* W_h    = (const float*)d_in[4];
    const float* bias   = (const float*)d_in[5];
    const float* fc_w   = (const float*)d_in[6];
    const float* fc_b   = (const float*)d_in[7];
    const void*  temp   = (n_in > 8) ? d_in[8] : nullptr;
    float*       out    = (float*)d_out;

    void *xin_ptr, *h_ptr, *logits_ptr;
    cudaGetSymbolAddress(&xin_ptr, g_xin);
    cudaGetSymbolAddress(&h_ptr, g_h);
    cudaGetSymbolAddress(&logits_ptr, g_logits);

    cudaFuncSetAttribute(rnn_persistent_kernel,
                         cudaFuncAttributeMaxDynamicSharedMemorySize, SM_TOTAL);

    build_weff_kernel<<<(HID * HID + 255) / 256, 256>>>(W_h);
    init_h_kernel<<<(BATCH * HID + 255) / 256, 256>>>(h_init);

    // xin = gather(emb, ids) @ W_in^T + bias
    {
        dim3 grid(HID / BN, (SEQ * BATCH) / BM);
        gemm_nt_kernel<true, true><<<grid, 256>>>(
            emb, ids, W_in, bias, (float*)xin_ptr, HID, EMB, HID);
    }

    // 1024 Euler steps, persistent HMMA kernel
    rnn_persistent_kernel<<<NCTA, 256, SM_TOTAL>>>();

    // logits = h @ fc_w^T + fc_b
    {
        dim3 grid((VOCAB + BN - 1) / BN, BATCH / BM);
        gemm_nt_kernel<false, true><<<grid, 256>>>(
            (const float*)h_ptr, nullptr, fc_w, fc_b, (float*)logits_ptr,
            VOCAB, HID, LDL);
    }

    softmax_kernel<<<BATCH, 256>>>(temp, out);
}

// round 11
// speedup vs baseline: 2.2764x; 1.2438x over previous
#include <cuda_runtime.h>
#include <cuda_bf16.h>
#include <stdint.h>
#include <math.h>

// ---------------------------------------------------------------------------
// CharRNN on GB300 (sm_103 baseline PTX; no tcgen05 -> warp-level HMMA).
// h_{t+1} = h_t + (h_t @ G^T) + dt*xin[t],  G = dt*(Wh - Wh^T - diff*I)
// R10: pipeline the recurrence. h is kept in gmem as fp32 (carry) PLUS bf16
// hi/lo (MMA operands, written by the epilogue). The step GEMM stages A via
// cp.async.cg into double-buffered SMEM (8 chunks of K=64) overlapped with
// ldmatrix+mma.sync.m16n8k16 bf16x3 (D += Ahi*Bhi + Ahi*Blo + Alo*Bhi).
// Persistent kernel, 128 CTAs (jt 0..31 x ks 0..3): tile M=128 x N=64 x K=512.
// ---------------------------------------------------------------------------

#define SEQ    1024
#define BATCH  128
#define HID    2048
#define EMB    512
#define VOCAB  50257
#define LDL    50260
#define DT     0.01f
#define DIFF   0.001f
#define KSPLIT 4
#define NCTA   128

#define BM 128
#define BN 64
#define BK 16

// SMEM layout (bytes).
// B: 64 rows x 520 bf16 (stride 1040B, 16B-phase rotates -> ldmatrix clean)
// A: 4 buffers (2 x hi/lo) of 128 rows x 72 bf16 (stride 144B)
#define SM_B_HI   0
#define SM_B_LO   66560
#define SM_A_HI0  133120
#define SM_A_LO0  151552
#define SM_A_HI1  169984
#define SM_A_LO1  188416
#define SM_TOTAL  206848

// scratch
__device__ float g_xin[(size_t)SEQ * BATCH * HID];
__device__ float g_weff[(size_t)HID * HID];          // G = dt*(Wh-Wh^T-diff I)
__device__ float g_h[2][BATCH * HID];                // fp32 carry (ping-pong)
__device__ __nv_bfloat16 g_hbf_hi[2][BATCH * HID];   // bf16 hi of h
__device__ __nv_bfloat16 g_hbf_lo[2][BATCH * HID];   // bf16 lo of h
__device__ float g_acc[KSPLIT][BATCH * HID];
__device__ float g_logits[(size_t)BATCH * LDL];
__device__ unsigned g_bar_gen;
__device__ unsigned g_bar_cnt;

// ---------------------------------------------------------------------------
__device__ __forceinline__ uint32_t smem_u32(const void* p) {
    uint32_t a;
    asm("{ .reg .u64 t; cvta.to.shared.u64 t, %1; cvt.u32.u64 %0, t; }"
        : "=r"(a) : "l"(p));
    return a;
}

#define LDSM_X4(r, addr) \
    asm volatile("ldmatrix.sync.aligned.m8n8.x4.shared.b16 {%0,%1,%2,%3}, [%4];" \
        : "=r"((r)[0]), "=r"((r)[1]), "=r"((r)[2]), "=r"((r)[3]) \
        : "r"(addr))

#define MMA16816(c, a, b) \
    asm volatile("mma.sync.aligned.m16n8k16.row.col.f32.bf16.bf16.f32 " \
        "{%0,%1,%2,%3}, {%4,%5,%6,%7}, {%8,%9}, {%0,%1,%2,%3};" \
        : "+f"((c)[0]), "+f"((c)[1]), "+f"((c)[2]), "+f"((c)[3]) \
        : "r"((a)[0]), "r"((a)[1]), "r"((a)[2]), "r"((a)[3]), \
          "r"((b)[0]), "r"((b)[1]))

#define CP_ASYNC16(dst, src) \
    asm volatile("cp.async.cg.shared.global [%0], [%1], 16;" \
        :: "r"(dst), "l"(src) : "memory")
#define CP_COMMIT() asm volatile("cp.async.commit_group;" ::: "memory")
#define CP_WAIT0()  asm volatile("cp.async.wait_group 0;" ::: "memory")

// ---------------------------------------------------------------------------
__global__ void build_weff_kernel(const float* __restrict__ Wh) {
    int idx = blockIdx.x * blockDim.x + threadIdx.x;
    if (idx < HID * HID) {
        int i = idx / HID, j = idx % HID;
        float v = Wh[idx] - Wh[j * HID + i];
        if (i == j) v -= DIFF;
        g_weff[idx] = DT * v;
    }
}

__global__ void init_h_kernel(const float* __restrict__ h0) {
    int i = blockIdx.x * blockDim.x + threadIdx.x;
    if (i < BATCH * HID) {
        float v = h0[i];
        g_h[0][i] = v;
        __nv_bfloat16 hi = __float2bfloat16_rn(v);
        g_hbf_hi[0][i] = hi;
        g_hbf_lo[0][i] = __float2bfloat16_rn(v - __bfloat162float(hi));
    }
}

// ---------------------------------------------------------------------------
// fp32 NT GEMM (xin + logits), proven in R3
// ---------------------------------------------------------------------------
template <bool GATHER, bool HAS_BIAS>
__global__ __launch_bounds__(256) void gemm_nt_kernel(
    const float* __restrict__ A, const int* __restrict__ gidx,
    const float* __restrict__ B, const float* __restrict__ bias,
    float* __restrict__ C, int N, int K, int ldc)
{
    __shared__ float As[BK][BM];
    __shared__ float Bs[BK][BN];

    const int tid = threadIdx.x;
    const int m0 = blockIdx.y * BM;
    const int n0 = blockIdx.x * BN;
    const int tr = tid >> 4;
    const int tc = tid & 15;
    const int ar0 = tid >> 2;
    const int ar1 = ar0 + 64;
    const int ac4 = tid & 3;

    const float* arow0;
    const float* arow1;
    if (GATHER) {
        arow0 = A + (size_t)gidx[m0 + ar0] * K;
        arow1 = A + (size_t)gidx[m0 + ar1] * K;
    } else {
        arow0 = A + (size_t)(m0 + ar0) * K;
        arow1 = A + (size_t)(m0 + ar1) * K;
    }
    const int   br     = tid >> 2;
    const bool  bvalid = (n0 + br) < N;
    const float* brow  = B + (size_t)(bvalid ? (n0 + br) : 0) * K;

    float acc[8][4];
    #pragma unroll
    for (int i = 0; i < 8; i++)
        #pragma unroll
        for (int j = 0; j < 4; j++) acc[i][j] = 0.f;

    for (int kt = 0; kt < K; kt += BK) {
        float4 va0 = *(const float4*)(arow0 + kt + ac4 * 4);
        float4 va1 = *(const float4*)(arow1 + kt + ac4 * 4);
        float4 vb  = bvalid ? *(const float4*)(brow + kt + ac4 * 4)
                            : make_float4(0.f, 0.f, 0.f, 0.f);
        __syncthreads();
        As[ac4 * 4 + 0][ar0] = va0.x; As[ac4 * 4 + 1][ar0] = va0.y;
        As[ac4 * 4 + 2][ar0] = va0.z; As[ac4 * 4 + 3][ar0] = va0.w;
        As[ac4 * 4 + 0][ar1] = va1.x; As[ac4 * 4 + 1][ar1] = va1.y;
        As[ac4 * 4 + 2][ar1] = va1.z; As[ac4 * 4 + 3][ar1] = va1.w;
        Bs[ac4 * 4 + 0][br] = vb.x;  Bs[ac4 * 4 + 1][br] = vb.y;
        Bs[ac4 * 4 + 2][br] = vb.z;  Bs[ac4 * 4 + 3][br] = vb.w;
        __syncthreads();

        #pragma unroll
        for (int k = 0; k < BK; k++) {
            float4 a0 = *(const float4*)&As[k][tr * 8];
            float4 a1 = *(const float4*)&As[k][tr * 8 + 4];
            float4 b4 = *(const float4*)&Bs[k][tc * 4];
            float av[8] = {a0.x, a0.y, a0.z, a0.w, a1.x, a1.y, a1.z, a1.w};
            float bv[4] = {b4.x, b4.y, b4.z, b4.w};
            #pragma unroll
            for (int i = 0; i < 8; i++)
                #pragma unroll
                for (int j = 0; j < 4; j++)
                    acc[i][j] = fmaf(av[i], bv[j], acc[i][j]);
        }
    }

    if (n0 + BN <= N) {
        #pragma unroll
        for (int i = 0; i < 8; i++) {
            int r = m0 + tr * 8 + i;
            int n = n0 + tc * 4;
            float4 st;
            if (HAS_BIAS) {
                st = make_float4(acc[i][0] + bias[n + 0], acc[i][1] + bias[n + 1],
                                 acc[i][2] + bias[n + 2], acc[i][3] + bias[n + 3]);
            } else {
                st = make_float4(acc[i][0], acc[i][1], acc[i][2], acc[i][3]);
            }
            *(float4*)(C + (size_t)r * ldc + n) = st;
        }
    } else {
        #pragma unroll
        for (int i = 0; i < 8; i++) {
            int r = m0 + tr * 8 + i;
            #pragma unroll
            for (int j = 0; j < 4; j++) {
                int n = n0 + tc * 4 + j;
                if (n < N)
                    C[(size_t)r * ldc + n] = acc[i][j] + (HAS_BIAS ? bias[n] : 0.f);
            }
        }
    }
}

// ---------------------------------------------------------------------------
__device__ __forceinline__ void grid_barrier()
{
    __syncthreads();
    if (threadIdx.x == 0) {
        __threadfence();
        unsigned gen = *(volatile unsigned*)&g_bar_gen;
        unsigned arrived = atomicAdd(&g_bar_cnt, 1u);
        if (arrived == NCTA - 1) {
            g_bar_cnt = 0;
            __threadfence();
            *(volatile unsigned*)&g_bar_gen = gen + 1;
        } else {
            while (*(volatile unsigned*)&g_bar_gen == gen) { }
        }
        __threadfence();
    }
    __syncthreads();
}

// ---------------------------------------------------------------------------
// Persistent HMMA recurrence, cp.async double-buffered A staging.
// Chunks: 8 x K=64. Per chunk per warp: 4 k16 x (8 LDSM.x4 + 24 MMA).
// ---------------------------------------------------------------------------
__global__ __launch_bounds__(256) void rnn_persistent_kernel()
{
    extern __shared__ char smem[];
    const uint32_t smem_base = smem_u32(smem);
    const int tid  = threadIdx.x;
    const int wid  = tid >> 5;
    const int lane = tid & 31;
    const int bid  = blockIdx.x;
    const int jt   = bid >> 2;
    const int ks   = bid & 3;
    const int n0   = jt * BN;
    const int kb   = ks * (HID / KSPLIT);   // 512-wide K slice

    // --- stage B = G[n0:n0+64, kb:kb+512] bf16 hi+lo (once) ---
    for (int i = tid; i < BN * 512; i += 256) {
        int n = i >> 9, k = i & 511;
        float w = g_weff[(size_t)(n0 + n) * HID + kb + k];
        __nv_bfloat16 hi = __float2bfloat16_rn(w);
        __nv_bfloat16 lo = __float2bfloat16_rn(w - __bfloat162float(hi));
        *(__nv_bfloat16*)(smem + SM_B_HI + n * 1040 + k * 2) = hi;
        *(__nv_bfloat16*)(smem + SM_B_LO + n * 1040 + k * 2) = lo;
    }
    __syncthreads();

    // A-buffer smem addresses (uint32 shared-space)
    const uint32_t abuf_hi[2] = { smem_base + SM_A_HI0, smem_base + SM_A_HI1 };
    const uint32_t abuf_lo[2] = { smem_base + SM_A_LO0, smem_base + SM_A_LO1 };

    // cp.async destination mapping: each thread does 4 hi + 4 lo transfers.
    // transfer i (0..1023): row = i>>3, k8 = i&7; dst = row*144 + k8*16.
    // Thread handles i = tid + q*256, q=0..3.
    uint32_t cp_dst[4];
    #pragma unroll
    for (int q = 0; q < 4; q++) {
        int i = tid + q * 256;
        cp_dst[q] = (uint32_t)((i >> 3) * 144 + (i & 7) * 16);
    }

    // ldmatrix lane offsets
    const int mw = (wid >> 1) * 32;          // warp m base
    const int nw = (wid & 1) * 32;           // warp n base
    const uint32_t a_row  = (uint32_t)(mw + (lane & 15));
    const uint32_t a_koff = (lane & 16) ? 16u : 0u;
    const uint32_t a_off0 = a_row * 144 + a_koff;
    const uint32_t a_off1 = (a_row + 16) * 144 + a_koff;
    const uint32_t b_row  = (uint32_t)((lane & 7) + ((lane & 16) ? 8 : 0));
    const uint32_t b_koff = (lane & 8) ? 16u : 0u;
    const uint32_t b_off0 = (uint32_t)(nw + 0  + b_row) * 1040 + b_koff;
    const uint32_t b_off1 = (uint32_t)(nw + 16 + b_row) * 1040 + b_koff;
    const uint32_t bhi_b = smem_base + SM_B_HI;
    const uint32_t blo_b = smem_base + SM_B_LO;

    const int ebase = bid * HID + tid * 8;   // epilogue: CTA owns batch row bid

    for (int t = 0; t < SEQ; t++) {
        const int p = t & 1;
        const char* __restrict__ src_hi = (const char*)g_hbf_hi[p];
        const char* __restrict__ src_lo = (const char*)g_hbf_lo[p];

        float c[2][4][4];
        #pragma unroll
        for (int i = 0; i < 2; i++)
            #pragma unroll
            for (int j = 0; j < 4; j++)
                #pragma unroll
                for (int q = 0; q < 4; q++) c[i][j][q] = 0.f;

        // prologue: issue chunk 0 loads into buffer 0
        {
            const size_t col0 = (size_t)(kb + 0 * 64) * 2;
            #pragma unroll
            for (int q = 0; q < 4; q++) {
                int i = tid + q * 256;
                size_t src_off = (size_t)(i >> 3) * (HID * 2) + col0 + (i & 7) * 16;
                CP_ASYNC16(abuf_hi[0] + cp_dst[q], src_hi + src_off);
                CP_ASYNC16(abuf_lo[0] + cp_dst[q], src_lo + src_off);
            }
            CP_COMMIT();
        }

        #pragma unroll 1
        for (int ch = 0; ch < 8; ch++) {
            const int b = ch & 1;
            CP_WAIT0();          // chunk ch resident in buffer b
            __syncthreads();     // + all warps done reading buffer b^1

            if (ch < 7) {        // issue chunk ch+1 into buffer b^1
                const size_t col = (size_t)(kb + (ch + 1) * 64) * 2;
                #pragma unroll
                for (int q = 0; q < 4; q++) {
                    int i = tid + q * 256;
                    size_t src_off = (size_t)(i >> 3) * (HID * 2) + col + (i & 7) * 16;
                    CP_ASYNC16(abuf_hi[b ^ 1] + cp_dst[q], src_hi + src_off);
                    CP_ASYNC16(abuf_lo[b ^ 1] + cp_dst[q], src_lo + src_off);
                }
                CP_COMMIT();
            }

            const uint32_t ahi = abuf_hi[b];
            const uint32_t alo = abuf_lo[b];
            const uint32_t bko = (uint32_t)(ch * 128);   // 64 bf16 = 128 bytes
            #pragma unroll
            for (int kk = 0; kk < 4; kk++) {
                const uint32_t ak = (uint32_t)(kk * 32);
                const uint32_t bk = bko + (uint32_t)(kk * 32);
                uint32_t ah0[4], ah1[4], al0[4], al1[4];
                uint32_t bh[8], bl[8];
                LDSM_X4(ah0, ahi + a_off0 + ak);
                LDSM_X4(ah1, ahi + a_off1 + ak);
                LDSM_X4(al0, alo + a_off0 + ak);
                LDSM_X4(al1, alo + a_off1 + ak);
                LDSM_X4(bh + 0, bhi_b + b_off0 + bk);
                LDSM_X4(bh + 4, bhi_b + b_off1 + bk);
                LDSM_X4(bl + 0, blo_b + b_off0 + bk);
                LDSM_X4(bl + 4, blo_b + b_off1 + bk);

                #pragma unroll
                for (int j = 0; j < 4; j++) {
                    MMA16816(c[0][j], ah0, bh + j * 2);
                    MMA16816(c[1][j], ah1, bh + j * 2);
                    MMA16816(c[0][j], ah0, bl + j * 2);
                    MMA16816(c[1][j], ah1, bl + j * 2);
                    MMA16816(c[0][j], al0, bh + j * 2);
                    MMA16816(c[1][j], al1, bh + j * 2);
                }
            }
        }

        // write split-K partials: warp tile 32x32 at (mw, n0+nw)
        {
            float* __restrict__ dst = g_acc[ks];
            #pragma unroll
            for (int i = 0; i < 2; i++) {
                int row = mw + i * 16 + (lane >> 2);
                #pragma unroll
                for (int j = 0; j < 4; j++) {
                    int col = n0 + nw + j * 8 + (lane & 3) * 2;
                    *(float2*)(dst + (size_t)row * HID + col) =
                        make_float2(c[i][j][0], c[i][j][1]);
                    *(float2*)(dst + (size_t)(row + 8) * HID + col) =
                        make_float2(c[i][j][2], c[i][j][3]);
                }
            }
        }

        grid_barrier();   // partials visible chip-wide

        // epilogue: h_new = h + sum_ks acc[ks] + dt*xin[t]; also bf16 hi/lo
        {
            const float* __restrict__ xrow = g_xin + (size_t)t * BATCH * HID;
            float* __restrict__ hout = g_h[p ^ 1];
            __nv_bfloat16* __restrict__ bh_out = g_hbf_hi[p ^ 1];
            __nv_bfloat16* __restrict__ bl_out = g_hbf_lo[p ^ 1];
            #pragma unroll
            for (int q = 0; q < 2; q++) {
                int i = ebase + q * 4;
                float4 s0 = __ldcg((const float4*)(g_acc[0] + i));
                float4 s1 = __ldcg((const float4*)(g_acc[1] + i));
                float4 s2 = __ldcg((const float4*)(g_acc[2] + i));
                float4 s3 = __ldcg((const float4*)(g_acc[3] + i));
                float4 hv = __ldcg((const float4*)(g_h[p] + i));
                float4 xv = *(const float4*)(xrow + i);
                float4 o;
                o.x = hv.x + (s0.x + s1.x + s2.x + s3.x) + DT * xv.x;
                o.y = hv.y + (s0.y + s1.y + s2.y + s3.y) + DT * xv.y;
                o.z = hv.z + (s0.z + s1.z + s2.z + s3.z) + DT * xv.z;
                o.w = hv.w + (s0.w + s1.w + s2.w + s3.w) + DT * xv.w;
                *(float4*)(hout + i) = o;

                __nv_bfloat162 h01 = __float22bfloat162_rn(make_float2(o.x, o.y));
                __nv_bfloat162 h23 = __float22bfloat162_rn(make_float2(o.z, o.w));
                float2 f01 = __bfloat1622float2(h01);
                float2 f23 = __bfloat1622float2(h23);
                __nv_bfloat162 l01 = __float22bfloat162_rn(
                    make_float2(o.x - f01.x, o.y - f01.y));
                __nv_bfloat162 l23 = __float22bfloat162_rn(
                    make_float2(o.z - f23.x, o.w - f23.y));
                *(uint2*)(bh_out + i) = make_uint2(*(uint32_t*)&h01, *(uint32_t*)&h23);
                *(uint2*)(bl_out + i) = make_uint2(*(uint32_t*)&l01, *(uint32_t*)&l23);
            }
        }

        grid_barrier();   // h_new (fp32 + bf16) visible before next staging
    }
}

// ---------------------------------------------------------------------------
__global__ __launch_bounds__(256) void softmax_kernel(const void* __restrict__ temp_raw,
                                                      float* __restrict__ out)
{
    __shared__ float red[256];
    const int b = blockIdx.x;
    const int tid = threadIdx.x;
    const float* __restrict__ row = g_logits + (size_t)b * LDL;
    float* __restrict__ orow = out + (size_t)b * VOCAB;

    float T = 1.0f;
    if (temp_raw) {
        int iv = *(const int*)temp_raw;
        float fv = __int_as_float(iv);
        if (iv >= 1 && iv <= 1000000) T = (float)iv;
        else if (fv > 1e-8f && fv < 1e8f) T = fv;
    }
    const float invT = 1.0f / T;

    float m = -3.4e38f;
    for (int v = tid; v < VOCAB; v += 256) m = fmaxf(m, row[v]);
    red[tid] = m; __syncthreads();
    for (int s = 128; s > 0; s >>= 1) {
        if (tid < s) red[tid] = fmaxf(red[tid], red[tid + s]);
        __syncthreads();
    }
    const float mx = red[0];
    __syncthreads();

    float sum = 0.f;
    for (int v = tid; v < VOCAB; v += 256) {
        float e = expf((row[v] - mx) * invT);
        orow[v] = e;
        sum += e;
    }
    red[tid] = sum; __syncthreads();
    for (int s = 128; s > 0; s >>= 1) {
        if (tid < s) red[tid] += red[tid + s];
        __syncthreads();
    }
    const float inv = 1.0f / red[0];
    for (int v = tid; v < VOCAB; v += 256) orow[v] *= inv;
}

// ---------------------------------------------------------------------------
extern "C" void kernel_launch(void* const* d_in, const int* in_sizes, int n_in,
                              void* d_out, int out_size)
{
    const int*   ids    = (const int*)d_in[0];
    const float* h_init = (const float*)d_in[1];
    const float* emb    = (const float*)d_in[2];
    const float* W_in   = (const float*)d_in[3];
    const float* W_h    = (const float*)d_in[4];
    const float* bias   = (const float*)d_in[5];
    const float* fc_w   = (const float*)d_in[6];
    const float* fc_b   = (const float*)d_in[7];
    const void*  temp   = (n_in > 8) ? d_in[8] : nullptr;
    float*       out    = (float*)d_out;

    void *xin_ptr, *h_ptr, *logits_ptr;
    cudaGetSymbolAddress(&xin_ptr, g_xin);
    cudaGetSymbolAddress(&h_ptr, g_h);
    cudaGetSymbolAddress(&logits_ptr, g_logits);

    cudaFuncSetAttribute(rnn_persistent_kernel,
                         cudaFuncAttributeMaxDynamicSharedMemorySize, SM_TOTAL);

    build_weff_kernel<<<(HID * HID + 255) / 256, 256>>>(W_h);
    init_h_kernel<<<(BATCH * HID + 255) / 256, 256>>>(h_init);

    // xin = gather(emb, ids) @ W_in^T + bias
    {
        dim3 grid(HID / BN, (SEQ * BATCH) / BM);
        gemm_nt_kernel<true, true><<<grid, 256>>>(
            emb, ids, W_in, bias, (float*)xin_ptr, HID, EMB, HID);
    }

    // 1024 Euler steps, persistent pipelined HMMA kernel
    rnn_persistent_kernel<<<NCTA, 256, SM_TOTAL>>>();

    // logits = h @ fc_w^T + fc_b
    {
        dim3 grid((VOCAB + BN - 1) / BN, BATCH / BM);
        gemm_nt_kernel<false, true><<<grid, 256>>>(
            (const float*)h_ptr, nullptr, fc_w, fc_b, (float*)logits_ptr,
            VOCAB, HID, LDL);
    }

    softmax_kernel<<<BATCH, 256>>>(temp, out);
}

// round 13
// speedup vs baseline: 2.5872x; 1.1366x over previous
#include <cuda_runtime.h>
#include <cuda_bf16.h>
#include <stdint.h>
#include <math.h>

// ---------------------------------------------------------------------------
// CharRNN on GB300 (sm_103 baseline PTX -> warp HMMA mma.sync bf16x3).
// R12 = R11 with the hmma_nt_kernel staging fix: A/B chunk staging loops
// covered only 64 of 128 K-columns (i<2048/i<1024, c4=(i&15)<<2) -> the MMA
// consumed unstaged SMEM -> NaN. Now i<4096/i<2048 with c4=(i&31)<<2.
// (1) recurrence: fine-grained per-column-group producer/consumer counters;
// (2) xin and logits GEMMs on bf16x3 HMMA.
// h_{t+1} = h_t + (h_t @ G^T) + dt*xin[t],  G = dt*(Wh - Wh^T - diff*I)
// ---------------------------------------------------------------------------

#define SEQ    1024
#define BATCH  128
#define HID    2048
#define EMB    512
#define VOCAB  50257
#define LDL    50260
#define DT     0.01f
#define DIFF   0.001f
#define NCTA   128
#define NGRP   32

// recurrence smem (bytes)
#define SM_B_HI   0
#define SM_B_LO   66560
#define SM_A_HI0  133120
#define SM_A_LO0  151552
#define SM_A_HI1  169984
#define SM_A_LO1  188416
#define SM_TOTAL  206848

// generic hmma gemm smem
#define GM_A_HI  0
#define GM_A_LO  34816
#define GM_B_HI  69632
#define GM_B_LO  87040
#define GM_TOTAL 104448

// scratch
__device__ float g_xin[(size_t)SEQ * BATCH * HID];
__device__ float g_weff[(size_t)HID * HID];          // G = dt*(Wh-Wh^T-diff I)
__device__ float g_h[2][BATCH * HID];                // fp32 carry (ping-pong)
__device__ __nv_bfloat16 g_hbf_hi[2][BATCH * HID];   // bf16 hi of h
__device__ __nv_bfloat16 g_hbf_lo[2][BATCH * HID];   // bf16 lo of h
__device__ float g_acc[4][BATCH * HID];              // split-K partials
__device__ float g_logits[(size_t)BATCH * LDL];
__device__ unsigned g_mma_cnt[NGRP];                 // partials of group ready
__device__ unsigned g_red_cnt[NGRP];                 // h cols of group ready

// ---------------------------------------------------------------------------
__device__ __forceinline__ uint32_t smem_u32(const void* p) {
    uint32_t a;
    asm("{ .reg .u64 t; cvta.to.shared.u64 t, %1; cvt.u32.u64 %0, t; }"
        : "=r"(a) : "l"(p));
    return a;
}

#define LDSM_X4(r, addr) \
    asm volatile("ldmatrix.sync.aligned.m8n8.x4.shared.b16 {%0,%1,%2,%3}, [%4];" \
        : "=r"((r)[0]), "=r"((r)[1]), "=r"((r)[2]), "=r"((r)[3]) \
        : "r"(addr))

#define MMA16816(c, a, b) \
    asm volatile("mma.sync.aligned.m16n8k16.row.col.f32.bf16.bf16.f32 " \
        "{%0,%1,%2,%3}, {%4,%5,%6,%7}, {%8,%9}, {%0,%1,%2,%3};" \
        : "+f"((c)[0]), "+f"((c)[1]), "+f"((c)[2]), "+f"((c)[3]) \
        : "r"((a)[0]), "r"((a)[1]), "r"((a)[2]), "r"((a)[3]), \
          "r"((b)[0]), "r"((b)[1]))

#define CP_ASYNC16(dst, src) \
    asm volatile("cp.async.cg.shared.global [%0], [%1], 16;" \
        :: "r"(dst), "l"(src) : "memory")
#define CP_COMMIT() asm volatile("cp.async.commit_group;" ::: "memory")
#define CP_WAIT0()  asm volatile("cp.async.wait_group 0;" ::: "memory")

__device__ __forceinline__ void spin_ge(const unsigned* p, unsigned thr) {
    while (*(volatile const unsigned*)p < thr) { }
}

// fp32 -> bf16 hi/lo pair (packed as 2 x uint32 of bf16x2)
__device__ __forceinline__ void split_bf16x4(float4 v, uint2& hi, uint2& lo) {
    __nv_bfloat162 h01 = __float22bfloat162_rn(make_float2(v.x, v.y));
    __nv_bfloat162 h23 = __float22bfloat162_rn(make_float2(v.z, v.w));
    float2 f01 = __bfloat1622float2(h01);
    float2 f23 = __bfloat1622float2(h23);
    __nv_bfloat162 l01 = __float22bfloat162_rn(make_float2(v.x - f01.x, v.y - f01.y));
    __nv_bfloat162 l23 = __float22bfloat162_rn(make_float2(v.z - f23.x, v.w - f23.y));
    hi = make_uint2(*(uint32_t*)&h01, *(uint32_t*)&h23);
    lo = make_uint2(*(uint32_t*)&l01, *(uint32_t*)&l23);
}

// ---------------------------------------------------------------------------
__global__ void build_weff_kernel(const float* __restrict__ Wh) {
    int idx = blockIdx.x * blockDim.x + threadIdx.x;
    if (idx < HID * HID) {
        int i = idx / HID, j = idx % HID;
        float v = Wh[idx] - Wh[j * HID + i];
        if (i == j) v -= DIFF;
        g_weff[idx] = DT * v;
    }
}

__global__ void init_h_kernel(const float* __restrict__ h0) {
    int i = blockIdx.x * blockDim.x + threadIdx.x;
    if (i < NGRP) { g_mma_cnt[i] = 0u; g_red_cnt[i] = 0u; }  // replay reset
    if (i < BATCH * HID) {
        float v = h0[i];
        g_h[0][i] = v;
        __nv_bfloat16 hi = __float2bfloat16_rn(v);
        g_hbf_hi[0][i] = hi;
        g_hbf_lo[0][i] = __float2bfloat16_rn(v - __bfloat162float(hi));
    }
}

// ---------------------------------------------------------------------------
// Generic NT HMMA GEMM (bf16x3): C[m,n] = sum_k A[m,k]*B[n,k] (+bias[n]).
// M multiple of 128 (grid.y tiles), K multiple of 128, N guarded.
// A optionally gathered by row via gidx. 256 threads, warp tile 32x32.
// ---------------------------------------------------------------------------
template <bool GATHER, bool HAS_BIAS>
__global__ __launch_bounds__(256) void hmma_nt_kernel(
    const float* __restrict__ A, const int* __restrict__ gidx,
    const float* __restrict__ B, const float* __restrict__ bias,
    float* __restrict__ C, int N, int K, int ldc)
{
    extern __shared__ char sm[];
    const uint32_t smb = smem_u32(sm);
    const int tid = threadIdx.x, wid = tid >> 5, lane = tid & 31;
    const int m0 = blockIdx.y * 128;
    const int n0 = blockIdx.x * 64;

    const int mw = (wid >> 1) * 32;
    const int nw = (wid & 1) * 32;
    const uint32_t a_off0 = (uint32_t)(mw + (lane & 15)) * 272
                          + ((lane & 16) ? 16u : 0u);
    const uint32_t a_off1 = a_off0 + 16u * 272u;
    const uint32_t b_row  = (uint32_t)((lane & 7) + ((lane & 16) ? 8 : 0));
    const uint32_t b_koff = (lane & 8) ? 16u : 0u;
    const uint32_t b_off0 = (uint32_t)(nw + b_row) * 272 + b_koff;
    const uint32_t b_off1 = (uint32_t)(nw + 16 + b_row) * 272 + b_koff;

    float c[2][4][4];
    #pragma unroll
    for (int i = 0; i < 2; i++)
        #pragma unroll
        for (int j = 0; j < 4; j++)
            #pragma unroll
            for (int q = 0; q < 4; q++) c[i][j][q] = 0.f;

    for (int kc = 0; kc < K; kc += 128) {
        __syncthreads();   // previous chunk fully consumed
        // stage A chunk: 128 rows x 128 cols = 128x32 float4
        for (int i = tid; i < 4096; i += 256) {
            int r = i >> 5, c4 = (i & 31) << 2;
            const float* arow = GATHER
                ? A + (size_t)__ldg(gidx + m0 + r) * K
                : A + (size_t)(m0 + r) * K;
            float4 v = *(const float4*)(arow + kc + c4);
            uint2 hi, lo;
            split_bf16x4(v, hi, lo);
            uint32_t off = (uint32_t)(r * 272 + c4 * 2);
            *(uint2*)(sm + GM_A_HI + off) = hi;
            *(uint2*)(sm + GM_A_LO + off) = lo;
        }
        // stage B chunk: 64 rows x 128 cols = 64x32 float4, zero-pad n >= N
        for (int i = tid; i < 2048; i += 256) {
            int r = i >> 5, c4 = (i & 31) << 2;
            int n = n0 + r;
            float4 v = (n < N) ? *(const float4*)(B + (size_t)n * K + kc + c4)
                               : make_float4(0.f, 0.f, 0.f, 0.f);
            uint2 hi, lo;
            split_bf16x4(v, hi, lo);
            uint32_t off = (uint32_t)(r * 272 + c4 * 2);
            *(uint2*)(sm + GM_B_HI + off) = hi;
            *(uint2*)(sm + GM_B_LO + off) = lo;
        }
        __syncthreads();

        #pragma unroll
        for (int kk = 0; kk < 8; kk++) {
            const uint32_t ak = (uint32_t)(kk * 32);
            uint32_t ah0[4], ah1[4], al0[4], al1[4], bh[8], bl[8];
            LDSM_X4(ah0, smb + GM_A_HI + a_off0 + ak);
            LDSM_X4(ah1, smb + GM_A_HI + a_off1 + ak);
            LDSM_X4(al0, smb + GM_A_LO + a_off0 + ak);
            LDSM_X4(al1, smb + GM_A_LO + a_off1 + ak);
            LDSM_X4(bh + 0, smb + GM_B_HI + b_off0 + ak);
            LDSM_X4(bh + 4, smb + GM_B_HI + b_off1 + ak);
            LDSM_X4(bl + 0, smb + GM_B_LO + b_off0 + ak);
            LDSM_X4(bl + 4, smb + GM_B_LO + b_off1 + ak);
            #pragma unroll
            for (int j = 0; j < 4; j++) {
                MMA16816(c[0][j], ah0, bh + j * 2);
                MMA16816(c[1][j], ah1, bh + j * 2);
                MMA16816(c[0][j], ah0, bl + j * 2);
                MMA16816(c[1][j], ah1, bl + j * 2);
                MMA16816(c[0][j], al0, bh + j * 2);
                MMA16816(c[1][j], al1, bh + j * 2);
            }
        }
    }

    // epilogue: bias + guarded store
    #pragma unroll
    for (int i = 0; i < 2; i++) {
        int row = m0 + mw + i * 16 + (lane >> 2);
        #pragma unroll
        for (int j = 0; j < 4; j++) {
            int col = n0 + nw + j * 8 + (lane & 3) * 2;
            if (col < N) {
                float b0 = HAS_BIAS ? bias[col] : 0.f;
                C[(size_t)row * ldc + col]       = c[i][j][0] + b0;
                C[(size_t)(row + 8) * ldc + col] = c[i][j][2] + b0;
            }
            if (col + 1 < N) {
                float b1 = HAS_BIAS ? bias[col + 1] : 0.f;
                C[(size_t)row * ldc + col + 1]       = c[i][j][1] + b1;
                C[(size_t)(row + 8) * ldc + col + 1] = c[i][j][3] + b1;
            }
        }
    }
}

// ---------------------------------------------------------------------------
// Persistent recurrence, fine-grained flag sync (no full grid barrier).
// CTA (jt = bid>>2, ks = bid&3): tile M=128 x N=64 (cols jt*64) x K=512
// (slice ks*512). Column group jt publishes g_red_cnt[jt] when h cols
// jt*64..+64 of the current step are written.
// ---------------------------------------------------------------------------
__global__ __launch_bounds__(256) void rnn_persistent_kernel()
{
    extern __shared__ char smem[];
    const uint32_t smem_base = smem_u32(smem);
    const int tid  = threadIdx.x;
    const int wid  = tid >> 5;
    const int lane = tid & 31;
    const int bid  = blockIdx.x;
    const int jt   = bid >> 2;
    const int ks   = bid & 3;
    const int n0   = jt * 64;
    const int kb   = ks * 512;

    // --- stage B = G[n0:n0+64, kb:kb+512] bf16 hi+lo (once) ---
    for (int i = tid; i < 64 * 512; i += 256) {
        int n = i >> 9, k = i & 511;
        float w = g_weff[(size_t)(n0 + n) * HID + kb + k];
        __nv_bfloat16 hi = __float2bfloat16_rn(w);
        __nv_bfloat16 lo = __float2bfloat16_rn(w - __bfloat162float(hi));
        *(__nv_bfloat16*)(smem + SM_B_HI + n * 1040 + k * 2) = hi;
        *(__nv_bfloat16*)(smem + SM_B_LO + n * 1040 + k * 2) = lo;
    }
    __syncthreads();

    const uint32_t abuf_hi[2] = { smem_base + SM_A_HI0, smem_base + SM_A_HI1 };
    const uint32_t abuf_lo[2] = { smem_base + SM_A_LO0, smem_base + SM_A_LO1 };

    uint32_t cp_dst[4];
    #pragma unroll
    for (int q = 0; q < 4; q++) {
        int i = tid + q * 256;
        cp_dst[q] = (uint32_t)((i >> 3) * 144 + (i & 7) * 16);
    }

    const int mw = (wid >> 1) * 32;
    const int nw = (wid & 1) * 32;
    const uint32_t a_off0 = (uint32_t)(mw + (lane & 15)) * 144
                          + ((lane & 16) ? 16u : 0u);
    const uint32_t a_off1 = a_off0 + 16u * 144u;
    const uint32_t b_row  = (uint32_t)((lane & 7) + ((lane & 16) ? 8 : 0));
    const uint32_t b_koff = (lane & 8) ? 16u : 0u;
    const uint32_t b_off0 = (uint32_t)(nw + 0  + b_row) * 1040 + b_koff;
    const uint32_t b_off1 = (uint32_t)(nw + 16 + b_row) * 1040 + b_koff;
    const uint32_t bhi_b = smem_base + SM_B_HI;
    const uint32_t blo_b = smem_base + SM_B_LO;

    // reduce mapping: rows ks*32..+32, cols n0..+64; 8 elems/thread
    const int rrow = ks * 32 + (tid >> 3);
    const int rcol = n0 + (tid & 7) * 8;
    const int ridx = rrow * HID + rcol;

    for (int t = 0; t < SEQ; t++) {
        const int p = t & 1;
        const char* __restrict__ src_hi = (const char*)g_hbf_hi[p];
        const char* __restrict__ src_lo = (const char*)g_hbf_lo[p];
        const unsigned thr_h = 4u * (unsigned)t;   // h^t ready threshold

        float c[2][4][4];
        #pragma unroll
        for (int i = 0; i < 2; i++)
            #pragma unroll
            for (int j = 0; j < 4; j++)
                #pragma unroll
                for (int q = 0; q < 4; q++) c[i][j][q] = 0.f;

        // prologue: gate chunk 0 on its producer group, then issue
        if (tid == 0) spin_ge(&g_red_cnt[ks * 8 + 0], thr_h);
        __syncthreads();
        {
            const size_t col0 = (size_t)kb * 2;
            #pragma unroll
            for (int q = 0; q < 4; q++) {
                int i = tid + q * 256;
                size_t so = (size_t)(i >> 3) * (HID * 2) + col0 + (i & 7) * 16;
                CP_ASYNC16(abuf_hi[0] + cp_dst[q], src_hi + so);
                CP_ASYNC16(abuf_lo[0] + cp_dst[q], src_lo + so);
            }
            CP_COMMIT();
        }

        #pragma unroll 1
        for (int ch = 0; ch < 8; ch++) {
            const int b = ch & 1;
            if (ch < 7 && tid == 0)
                spin_ge(&g_red_cnt[ks * 8 + ch + 1], thr_h);
            CP_WAIT0();          // chunk ch resident (only group in flight)
            __syncthreads();     // gate passed + buffer b^1 free

            if (ch < 7) {
                const size_t col = (size_t)(kb + (ch + 1) * 64) * 2;
                #pragma unroll
                for (int q = 0; q < 4; q++) {
                    int i = tid + q * 256;
                    size_t so = (size_t)(i >> 3) * (HID * 2) + col + (i & 7) * 16;
                    CP_ASYNC16(abuf_hi[b ^ 1] + cp_dst[q], src_hi + so);
                    CP_ASYNC16(abuf_lo[b ^ 1] + cp_dst[q], src_lo + so);
                }
                CP_COMMIT();
            }

            const uint32_t ahi = abuf_hi[b];
            const uint32_t alo = abuf_lo[b];
            const uint32_t bko = (uint32_t)(ch * 128);
            #pragma unroll
            for (int kk = 0; kk < 4; kk++) {
                const uint32_t ak = (uint32_t)(kk * 32);
                const uint32_t bk = bko + (uint32_t)(kk * 32);
                uint32_t ah0[4], ah1[4], al0[4], al1[4];
                uint32_t bh[8], bl[8];
                LDSM_X4(ah0, ahi + a_off0 + ak);
                LDSM_X4(ah1, ahi + a_off1 + ak);
                LDSM_X4(al0, alo + a_off0 + ak);
                LDSM_X4(al1, alo + a_off1 + ak);
                LDSM_X4(bh + 0, bhi_b + b_off0 + bk);
                LDSM_X4(bh + 4, bhi_b + b_off1 + bk);
                LDSM_X4(bl + 0, blo_b + b_off0 + bk);
                LDSM_X4(bl + 4, blo_b + b_off1 + bk);
                #pragma unroll
                for (int j = 0; j < 4; j++) {
                    MMA16816(c[0][j], ah0, bh + j * 2);
                    MMA16816(c[1][j], ah1, bh + j * 2);
                    MMA16816(c[0][j], ah0, bl + j * 2);
                    MMA16816(c[1][j], ah1, bl + j * 2);
                    MMA16816(c[0][j], al0, bh + j * 2);
                    MMA16816(c[1][j], al1, bh + j * 2);
                }
            }
        }

        // wait: previous step's reducers of OUR group finished reading partials
        if (tid == 0) spin_ge(&g_red_cnt[jt], thr_h);
        __syncthreads();

        // write split-K partials: warp tile 32x32 at (mw, n0+nw)
        {
            float* __restrict__ dst = g_acc[ks];
            #pragma unroll
            for (int i = 0; i < 2; i++) {
                int row = mw + i * 16 + (lane >> 2);
                #pragma unroll
                for (int j = 0; j < 4; j++) {
                    int col = n0 + nw + j * 8 + (lane & 3) * 2;
                    *(float2*)(dst + (size_t)row * HID + col) =
                        make_float2(c[i][j][0], c[i][j][1]);
                    *(float2*)(dst + (size_t)(row + 8) * HID + col) =
                        make_float2(c[i][j][2], c[i][j][3]);
                }
            }
        }
        __threadfence();
        __syncthreads();
        if (tid == 0) {
            atomicAdd(&g_mma_cnt[jt], 1u);
            spin_ge(&g_mma_cnt[jt], 4u * (unsigned)(t + 1));
        }
        __syncthreads();
        __threadfence();

        // reduce + h update for rows ks*32..+32, cols n0..+64
        {
            const float* __restrict__ xrow = g_xin + (size_t)t * BATCH * HID;
            float* __restrict__ hout = g_h[p ^ 1];
            __nv_bfloat16* __restrict__ bh_out = g_hbf_hi[p ^ 1];
            __nv_bfloat16* __restrict__ bl_out = g_hbf_lo[p ^ 1];
            #pragma unroll
            for (int q = 0; q < 2; q++) {
                int i = ridx + q * 4;
                float4 s0 = __ldcg((const float4*)(g_acc[0] + i));
                float4 s1 = __ldcg((const float4*)(g_acc[1] + i));
                float4 s2 = __ldcg((const float4*)(g_acc[2] + i));
                float4 s3 = __ldcg((const float4*)(g_acc[3] + i));
                float4 hv = __ldcg((const float4*)(g_h[p] + i));
                float4 xv = *(const float4*)(xrow + i);
                float4 o;
                o.x = hv.x + (s0.x + s1.x + s2.x + s3.x) + DT * xv.x;
                o.y = hv.y + (s0.y + s1.y + s2.y + s3.y) + DT * xv.y;
                o.z = hv.z + (s0.z + s1.z + s2.z + s3.z) + DT * xv.z;
                o.w = hv.w + (s0.w + s1.w + s2.w + s3.w) + DT * xv.w;
                *(float4*)(hout + i) = o;
                uint2 hi, lo;
                split_bf16x4(o, hi, lo);
                *(uint2*)(bh_out + i) = hi;
                *(uint2*)(bl_out + i) = lo;
            }
        }
        __threadfence();
        __syncthreads();
        if (tid == 0) atomicAdd(&g_red_cnt[jt], 1u);   // h^{t+1} cols published
    }
}

// ---------------------------------------------------------------------------
__global__ __launch_bounds__(256) void softmax_kernel(const void* __restrict__ temp_raw,
                                                      float* __restrict__ out)
{
    __shared__ float red[256];
    const int b = blockIdx.x;
    const int tid = threadIdx.x;
    const float* __restrict__ row = g_logits + (size_t)b * LDL;
    float* __restrict__ orow = out + (size_t)b * VOCAB;

    float T = 1.0f;
    if (temp_raw) {
        int iv = *(const int*)temp_raw;
        float fv = __int_as_float(iv);
        if (iv >= 1 && iv <= 1000000) T = (float)iv;
        else if (fv > 1e-8f && fv < 1e8f) T = fv;
    }
    const float invT = 1.0f / T;

    float m = -3.4e38f;
    for (int v = tid; v < VOCAB; v += 256) m = fmaxf(m, row[v]);
    red[tid] = m; __syncthreads();
    for (int s = 128; s > 0; s >>= 1) {
        if (tid < s) red[tid] = fmaxf(red[tid], red[tid + s]);
        __syncthreads();
    }
    const float mx = red[0];
    __syncthreads();

    float sum = 0.f;
    for (int v = tid; v < VOCAB; v += 256) {
        float e = expf((row[v] - mx) * invT);
        orow[v] = e;
        sum += e;
    }
    red[tid] = sum; __syncthreads();
    for (int s = 128; s > 0; s >>= 1) {
        if (tid < s) red[tid] += red[tid + s];
        __syncthreads();
    }
    const float inv = 1.0f / red[0];
    for (int v = tid; v < VOCAB; v += 256) orow[v] *= inv;
}

// ---------------------------------------------------------------------------
extern "C" void kernel_launch(void* const* d_in, const int* in_sizes, int n_in,
                              void* d_out, int out_size)
{
    const int*   ids    = (const int*)d_in[0];
    const float* h_init = (const float*)d_in[1];
    const float* emb    = (const float*)d_in[2];
    const float* W_in   = (const float*)d_in[3];
    const float* W_h    = (const float*)d_in[4];
    const float* bias   = (const float*)d_in[5];
    const float* fc_w   = (const float*)d_in[6];
    const float* fc_b   = (const float*)d_in[7];
    const void*  temp   = (n_in > 8) ? d_in[8] : nullptr;
    float*       out    = (float*)d_out;

    void *xin_ptr, *h_ptr, *logits_ptr;
    cudaGetSymbolAddress(&xin_ptr, g_xin);
    cudaGetSymbolAddress(&h_ptr, g_h);
    cudaGetSymbolAddress(&logits_ptr, g_logits);

    cudaFuncSetAttribute(rnn_persistent_kernel,
                         cudaFuncAttributeMaxDynamicSharedMemorySize, SM_TOTAL);
    cudaFuncSetAttribute(hmma_nt_kernel<true, true>,
                         cudaFuncAttributeMaxDynamicSharedMemorySize, GM_TOTAL);
    cudaFuncSetAttribute(hmma_nt_kernel<false, true>,
                         cudaFuncAttributeMaxDynamicSharedMemorySize, GM_TOTAL);

    build_weff_kernel<<<(HID * HID + 255) / 256, 256>>>(W_h);
    init_h_kernel<<<(BATCH * HID + 255) / 256, 256>>>(h_init);

    // xin = gather(emb, ids) @ W_in^T + bias : M=131072, N=2048, K=512 (HMMA)
    hmma_nt_kernel<true, true><<<dim3(HID / 64, (SEQ * BATCH) / 128), 256, GM_TOTAL>>>(
        emb, ids, W_in, bias, (float*)xin_ptr, HID, EMB, HID);

    // 1024 Euler steps, persistent flag-synced HMMA kernel
    rnn_persistent_kernel<<<NCTA, 256, SM_TOTAL>>>();

    // logits = h_final @ fc_w^T + fc_b : M=128, N=50257, K=2048 (HMMA)
    hmma_nt_kernel<false, true><<<dim3((VOCAB + 63) / 64, 1), 256, GM_TOTAL>>>(
        (const float*)h_ptr, nullptr, fc_w, fc_b, (float*)logits_ptr,
        VOCAB, HID, LDL);

    softmax_kernel<<<BATCH, 256>>>(temp, out);
}